// round 16
// baseline (speedup 1.0000x reference)
#include <cuda_runtime.h>
#include <cuda_bf16.h>
#include <cstdint>

// Problem constants
#define B_     2
#define T_     8
#define H_     14
#define W_     14
#define S_     196          // H_*W_
#define N_     1568         // T_*S_
#define NPAD   1600         // padded rows per (b,h): 25 * 64
#define DIM_   768
#define HEADS_ 12
#define HD_    64
#define MROWS  (B_ * N_)    // 3136
#define MPAD   3200         // 25 * 128
#define NBIAS  36           // 14 (h) + 14 (w) + 8 (t)

// fp32 scratch (q needed for relbias)
__device__ float g_q[(size_t)B_ * HEADS_ * N_ * HD_];
__device__ float g_bias[(size_t)B_ * HEADS_ * N_ * NBIAS];
// packed k coordinates: kh | kw<<8 | kt<<16, bit31 = out-of-range
__device__ uint32_t g_kcoord[NPAD];

// split-bf16 scratch for the two projection GEMMs
__device__ __nv_bfloat16 g_xh[(size_t)MPAD * DIM_];
__device__ __nv_bfloat16 g_xl[(size_t)MPAD * DIM_];
__device__ __nv_bfloat16 g_wh[(size_t)3 * DIM_ * DIM_];
__device__ __nv_bfloat16 g_wl[(size_t)3 * DIM_ * DIM_];
__device__ __nv_bfloat16 g_ph[(size_t)DIM_ * DIM_];
__device__ __nv_bfloat16 g_pl[(size_t)DIM_ * DIM_];
// attention output, split (pad rows stay statically zero — never written)
__device__ __nv_bfloat16 g_oh[(size_t)MPAD * DIM_];
__device__ __nv_bfloat16 g_ol[(size_t)MPAD * DIM_];

// split-bf16 attention operands (padded; pad rows statically zero)
#define ASZ ((size_t)B_ * HEADS_ * NPAD * HD_)
__device__ __nv_bfloat16 g_aqh[ASZ], g_aql[ASZ];   // Q pre-scaled by 0.125
__device__ __nv_bfloat16 g_akh[ASZ], g_akl[ASZ];
__device__ __nv_bfloat16 g_avh[ASZ], g_avl[ASZ];

// ---------------------------------------------------------------------------
// Helpers (sm_80-family only — compile clean to plain compute_103)
// ---------------------------------------------------------------------------
__device__ __forceinline__ uint32_t smem_u32(const void* p) {
    uint32_t a;
    asm("{ .reg .u64 t; cvta.to.shared.u64 t, %1; cvt.u32.u64 %0, t; }"
        : "=r"(a) : "l"(p));
    return a;
}

__device__ __forceinline__ uint32_t swz(uint32_t x) {
    return x ^ ((x >> 3) & 0x70);
}

#define CP_ASYNC16(s, g) \
    asm volatile("cp.async.cg.shared.global [%0], [%1], 16;" :: "r"(s), "l"(g))

#define LDSM4(r, a) \
    asm volatile("ldmatrix.sync.aligned.m8n8.x4.shared.b16 {%0,%1,%2,%3}, [%4];" \
        : "=r"((r)[0]), "=r"((r)[1]), "=r"((r)[2]), "=r"((r)[3]) : "r"(a))

#define LDSM4T(r, a) \
    asm volatile("ldmatrix.sync.aligned.m8n8.x4.trans.shared.b16 {%0,%1,%2,%3}, [%4];" \
        : "=r"((r)[0]), "=r"((r)[1]), "=r"((r)[2]), "=r"((r)[3]) : "r"(a))

#define MMA16816(d, a, b0, b1) \
    asm volatile("mma.sync.aligned.m16n8k16.row.col.f32.bf16.bf16.f32 " \
        "{%0,%1,%2,%3},{%4,%5,%6,%7},{%8,%9},{%0,%1,%2,%3};" \
        : "+f"((d)[0]), "+f"((d)[1]), "+f"((d)[2]), "+f"((d)[3]) \
        : "r"((a)[0]), "r"((a)[1]), "r"((a)[2]), "r"((a)[3]), "r"(b0), "r"(b1))

// pack two fp32 into bf16x2 hi/lo split (fast: packed cvt + shift/sub)
__device__ __forceinline__ void split2(float p0, float p1,
                                       uint32_t& hi, uint32_t& lo) {
    uint32_t h;
    asm("cvt.rn.bf16x2.f32 %0, %1, %2;" : "=r"(h) : "f"(p1), "f"(p0));
    float h0 = __uint_as_float(h << 16);
    float h1 = __uint_as_float(h & 0xffff0000u);
    float l0 = p0 - h0, l1 = p1 - h1;
    asm("cvt.rn.bf16x2.f32 %0, %1, %2;" : "=r"(lo) : "f"(l1), "f"(l0));
    hi = h;
}

// ---------------------------------------------------------------------------
// Merged split conversion (one launch):
//   [0, CVT_NXP)   : x      -> g_xh/g_xl  (pad rows zero)
//   [+CVT_NW)      : qkv_w  -> g_wh/g_wl
//   [+CVT_NP)      : proj_w -> g_ph/g_pl
//   [+NPAD)        : packed k-coordinate table g_kcoord
// ---------------------------------------------------------------------------
#define CVT_NX  (MROWS * DIM_)
#define CVT_NXP (MPAD * DIM_)
#define CVT_NW  (3 * DIM_ * DIM_)
#define CVT_NP  (DIM_ * DIM_)
#define CVT_TOTAL (CVT_NXP + CVT_NW + CVT_NP + NPAD)

__global__ __launch_bounds__(256) void split_all(const float* __restrict__ x,
                                                 const float* __restrict__ qw,
                                                 const float* __restrict__ pw) {
    int i = blockIdx.x * blockDim.x + threadIdx.x;
    if (i >= CVT_TOTAL) return;
    if (i >= CVT_NXP + CVT_NW + CVT_NP) {
        int kg = i - (CVT_NXP + CVT_NW + CVT_NP);
        uint32_t pc = 0x80000000u;
        if (kg < N_) {
            int ktt = kg / S_;
            int krem = kg - ktt * S_;
            int khh = krem / W_;
            int kww = krem - khh * W_;
            pc = (uint32_t)khh | ((uint32_t)kww << 8) | ((uint32_t)ktt << 16);
        }
        g_kcoord[kg] = pc;
        return;
    }
    float v;
    __nv_bfloat16 *hi, *lo;
    int o;
    if (i < CVT_NXP) {
        o = i;
        v = (o < CVT_NX) ? x[o] : 0.f;
        hi = g_xh; lo = g_xl;
    } else if (i < CVT_NXP + CVT_NW) {
        o = i - CVT_NXP;
        v = qw[o];
        hi = g_wh; lo = g_wl;
    } else {
        o = i - CVT_NXP - CVT_NW;
        v = pw[o];
        hi = g_ph; lo = g_pl;
    }
    __nv_bfloat16 h = __float2bfloat16(v);
    hi[o] = h;
    lo[o] = __float2bfloat16(v - __bfloat162float(h));
}

// ---------------------------------------------------------------------------
// Warp-MMA split-bf16 GEMM, single-buffered 64KB smem, 2 CTAs/SM (R11 path).
// ---------------------------------------------------------------------------
#define OFF_AH 0u
#define OFF_AL 16384u
#define OFF_BH 32768u
#define OFF_BL 49152u
#define GSMEM  65536

__device__ __forceinline__ void gemm_load(uint32_t sb,
        const __nv_bfloat16* Ahp, const __nv_bfloat16* Alp,
        const __nv_bfloat16* Bhp, const __nv_bfloat16* Blp,
        int m0, int n0, int k0, int tid) {
    const int grow = tid >> 3, gch = tid & 7;
#pragma unroll
    for (int p = 0; p < 4; p++) {
        int row = grow + p * 32;
        uint32_t sw = swz((uint32_t)(row * 128 + gch * 16));
        size_t ga = (size_t)(m0 + row) * DIM_ + k0 + gch * 8;
        size_t gb = (size_t)(n0 + row) * DIM_ + k0 + gch * 8;
        CP_ASYNC16(sb + OFF_AH + sw, Ahp + ga);
        CP_ASYNC16(sb + OFF_AL + sw, Alp + ga);
        CP_ASYNC16(sb + OFF_BH + sw, Bhp + gb);
        CP_ASYNC16(sb + OFF_BL + sw, Blp + gb);
    }
    asm volatile("cp.async.commit_group;");
}

__global__ __launch_bounds__(256, 2) void mma_gemm(int mode,
                                                   const float* __restrict__ pb,
                                                   float* __restrict__ out) {
    extern __shared__ char sm[];
    const uint32_t sb = smem_u32(sm);
    const int tid = threadIdx.x;
    const int lane = tid & 31, wid = tid >> 5;
    const int wm = wid & 3;
    const int wn = wid >> 2;
    const int m0 = blockIdx.y * 128;
    const int n0 = blockIdx.x * 128;

    const __nv_bfloat16* Ahp = (mode == 0) ? g_xh : g_oh;
    const __nv_bfloat16* Alp = (mode == 0) ? g_xl : g_ol;
    const __nv_bfloat16* Bhp = (mode == 0) ? g_wh : g_ph;
    const __nv_bfloat16* Blp = (mode == 0) ? g_wl : g_pl;

    float acc[2][8][4];
#pragma unroll
    for (int a = 0; a < 2; a++)
#pragma unroll
        for (int na = 0; na < 8; na++)
#pragma unroll
            for (int r = 0; r < 4; r++) acc[a][na][r] = 0.f;

    const int ar = lane & 15, akh = lane >> 4;
    const uint32_t a_base = (uint32_t)((wm * 32 + ar) * 128 + akh * 16);
    const int br = lane & 7, bsel = lane >> 3;
    const uint32_t b_base =
        (uint32_t)((wn * 64 + (bsel >> 1) * 8 + br) * 128 + (bsel & 1) * 16);

    for (int c = 0; c < DIM_ / 64; c++) {
        gemm_load(sb, Ahp, Alp, Bhp, Blp, m0, n0, c * 64, tid);
        asm volatile("cp.async.wait_group 0;" ::: "memory");
        __syncthreads();

#pragma unroll
        for (int ks = 0; ks < 4; ks++) {
            const uint32_t kb = ks * 32;
            uint32_t ah[2][4], bh[4][4];
#pragma unroll
            for (int a = 0; a < 2; a++)
                LDSM4(ah[a], sb + OFF_AH + swz(a_base + a * 2048 + kb));
#pragma unroll
            for (int g = 0; g < 4; g++)
                LDSM4(bh[g], sb + OFF_BH + swz(b_base + g * 2048 + kb));
#pragma unroll
            for (int a = 0; a < 2; a++)
#pragma unroll
                for (int g = 0; g < 4; g++) {
                    MMA16816(acc[a][2 * g + 0], ah[a], bh[g][0], bh[g][1]);
                    MMA16816(acc[a][2 * g + 1], ah[a], bh[g][2], bh[g][3]);
                }
            {
                uint32_t al[2][4];
#pragma unroll
                for (int a = 0; a < 2; a++)
                    LDSM4(al[a], sb + OFF_AL + swz(a_base + a * 2048 + kb));
#pragma unroll
                for (int a = 0; a < 2; a++)
#pragma unroll
                    for (int g = 0; g < 4; g++) {
                        MMA16816(acc[a][2 * g + 0], al[a], bh[g][0], bh[g][1]);
                        MMA16816(acc[a][2 * g + 1], al[a], bh[g][2], bh[g][3]);
                    }
            }
#pragma unroll
            for (int g = 0; g < 4; g++)
                LDSM4(bh[g], sb + OFF_BL + swz(b_base + g * 2048 + kb));
#pragma unroll
            for (int a = 0; a < 2; a++)
#pragma unroll
                for (int g = 0; g < 4; g++) {
                    MMA16816(acc[a][2 * g + 0], ah[a], bh[g][0], bh[g][1]);
                    MMA16816(acc[a][2 * g + 1], ah[a], bh[g][2], bh[g][3]);
                }
        }
        __syncthreads();
    }

    const int mr = m0 + wm * 32 + lane / 4;
    const int nc0 = (lane & 3) * 2;
    if (mode == 0) {
        const int ncb = n0 + wn * 64;
        const int s = ncb / DIM_;                 // 0=q,1=k,2=v
        const int head = (ncb % DIM_) / HD_;
#pragma unroll
        for (int a = 0; a < 2; a++)
#pragma unroll
            for (int hf = 0; hf < 2; hf++) {
                int m = mr + a * 16 + hf * 8;
                if (m < MROWS) {
                    int bb = m / N_;
                    int nn = m - bb * N_;
                    size_t bh = (size_t)bb * HEADS_ + head;
                    size_t arow = (bh * NPAD + nn) * HD_;
#pragma unroll
                    for (int na = 0; na < 8; na++) {
                        int col = na * 8 + nc0;
                        float v0 = acc[a][na][hf * 2];
                        float v1 = acc[a][na][hf * 2 + 1];
                        uint32_t hi, lo;
                        if (s == 0) {
                            float* qrow = g_q + (bh * N_ + nn) * HD_;
                            qrow[col] = v0; qrow[col + 1] = v1;   // unscaled (relbias)
                            split2(v0 * 0.125f, v1 * 0.125f, hi, lo);
                            *(uint32_t*)(g_aqh + arow + col) = hi;
                            *(uint32_t*)(g_aql + arow + col) = lo;
                        } else if (s == 1) {
                            split2(v0, v1, hi, lo);
                            *(uint32_t*)(g_akh + arow + col) = hi;
                            *(uint32_t*)(g_akl + arow + col) = lo;
                        } else {
                            split2(v0, v1, hi, lo);
                            *(uint32_t*)(g_avh + arow + col) = hi;
                            *(uint32_t*)(g_avl + arow + col) = lo;
                        }
                    }
                }
            }
    } else {
        const int ncb = n0 + wn * 64;
#pragma unroll
        for (int a = 0; a < 2; a++)
#pragma unroll
            for (int hf = 0; hf < 2; hf++) {
                int m = mr + a * 16 + hf * 8;
                if (m < MROWS) {
                    float* orow = out + (size_t)m * DIM_ + ncb;
#pragma unroll
                    for (int na = 0; na < 8; na++) {
                        int cc = na * 8 + nc0;
                        orow[cc]     = acc[a][na][hf * 2]     + pb[ncb + cc];
                        orow[cc + 1] = acc[a][na][hf * 2 + 1] + pb[ncb + cc + 1];
                    }
                }
            }
    }
}

// ---------------------------------------------------------------------------
// Relative position bias precompute (one warp per (b,h,q); unscaled q).
// ---------------------------------------------------------------------------
__global__ __launch_bounds__(256) void relbias(const float* __restrict__ rel_h,
                                               const float* __restrict__ rel_w,
                                               const float* __restrict__ rel_t) {
    const int warp = (blockIdx.x * blockDim.x + threadIdx.x) >> 5;
    const int lane = threadIdx.x & 31;
    if (warp >= B_ * HEADS_ * N_) return;
    const int q = warp % N_;
    const int qt = q / S_;
    const int qrem = q - qt * S_;
    const int qh = qrem / W_;
    const int qw = qrem - qh * W_;

    const float* qv = g_q + (size_t)warp * HD_;
    const float qa = qv[lane];
    const float qb = qv[lane + 32];
    float* out = g_bias + (size_t)warp * NBIAS;

#pragma unroll 4
    for (int j = 0; j < NBIAS; j++) {
        const float* r;
        if (j < 14)       r = rel_h + (size_t)(qh - j + 13) * HD_;
        else if (j < 28)  r = rel_w + (size_t)(qw - (j - 14) + 13) * HD_;
        else              r = rel_t + (size_t)(qt - (j - 28) + 7) * HD_;
        float p = qa * r[lane] + qb * r[lane + 32];
#pragma unroll
        for (int m = 16; m >= 1; m >>= 1) p += __shfl_xor_sync(0xffffffffu, p, m);
        if (lane == 0) out[j] = p;
    }
}

// ---------------------------------------------------------------------------
// Tensor-core flash attention, 3 CTAs/SM:
//  - Q staged through stage-1 KV slots (no dedicated Q smem)
//  - k-coordinates read from global (L1/L2-cached uint2 loads, no smem table)
//  - fixed-max softmax, paired float2 bias, precomputed LDSM addresses
//  - smem = 2 x 32KB KV stages + 9KB bias = 74.75KB -> 3 CTAs/SM
// ---------------------------------------------------------------------------
#define AT_KH 0u
#define AT_KL 8192u
#define AT_VH 16384u
#define AT_VL 24576u
#define AT_STAGE 32768u
#define AT_BI 65536u
#define AT_SMEM (65536 + 64 * NBIAS * 4)   // 74752

__device__ __forceinline__ void attn_load_kv(uint32_t sb, uint32_t so,
                                             size_t abase, int k0, int tid) {
#pragma unroll
    for (int p = 0; p < 4; p++) {
        int idx = tid + p * 128;
        int row = idx >> 3, ch = idx & 7;
        uint32_t sw = swz((uint32_t)(row * 128 + ch * 16));
        size_t g = abase + (size_t)(k0 + row) * HD_ + ch * 8;
        CP_ASYNC16(sb + so + AT_KH + sw, g_akh + g);
        CP_ASYNC16(sb + so + AT_KL + sw, g_akl + g);
        CP_ASYNC16(sb + so + AT_VH + sw, g_avh + g);
        CP_ASYNC16(sb + so + AT_VL + sw, g_avl + g);
    }
    asm volatile("cp.async.commit_group;");
}

__global__ __launch_bounds__(128, 3) void attn_tc() {
    extern __shared__ char sm[];
    const uint32_t sb = smem_u32(sm);
    float* Bi = (float*)(sm + AT_BI);
    const int b = blockIdx.z, h = blockIdx.y, q0 = blockIdx.x * 64;
    const int tid = threadIdx.x, lane = tid & 31, warp = tid >> 5;
    const size_t bh = (size_t)b * HEADS_ + h;
    const size_t abase = bh * NPAD * HD_;
    const int NT = NPAD / 64;                 // 25 k-tiles

    // Group A: Q tiles (hi/lo) staged into stage-1 KH/KL slots
#pragma unroll
    for (int p = 0; p < 4; p++) {
        int idx = tid + p * 128;
        int row = idx >> 3, ch = idx & 7;
        uint32_t sw = swz((uint32_t)(row * 128 + ch * 16));
        size_t g = abase + (size_t)(q0 + row) * HD_ + ch * 8;
        CP_ASYNC16(sb + AT_STAGE + AT_KH + sw, g_aqh + g);
        CP_ASYNC16(sb + AT_STAGE + AT_KL + sw, g_aql + g);
    }
    asm volatile("cp.async.commit_group;");
    // Group B: KV tile 0 -> stage 0
    attn_load_kv(sb, 0u, abase, 0, tid);
    // Bias into paired layout: Bi2[(j*32 + pair)*2 + half], pair rows (r, r+8)
    for (int i = tid; i < 64 * NBIAS; i += 128) {
        int qr = i / NBIAS, j = i - qr * NBIAS;
        int qg = q0 + qr;
        float v = (qg < N_) ? g_bias[(bh * N_ + qg) * NBIAS + j] : 0.f;
        int wq = qr >> 4, within = qr & 15;
        int half = within >> 3, sub = within & 7;
        Bi[(j * 32 + wq * 8 + sub) * 2 + half] = v;
    }
    asm volatile("cp.async.wait_group 1;" ::: "memory");   // Q staged
    __syncthreads();

    // Q fragments (held for the whole kernel) from stage-1 slots
    uint32_t qfh[4][4], qfl[4][4];
    {
        const uint32_t a_base =
            (uint32_t)((warp * 16 + (lane & 15)) * 128 + (lane >> 4) * 16);
#pragma unroll
        for (int kc = 0; kc < 4; kc++) {
            LDSM4(qfh[kc], sb + AT_STAGE + AT_KH + swz(a_base + kc * 32));
            LDSM4(qfl[kc], sb + AT_STAGE + AT_KL + swz(a_base + kc * 32));
        }
    }
    __syncthreads();   // all warps done reading stage 1 before KV1 overwrites

    // Group C: KV tile 1 -> stage 1
    attn_load_kv(sb, AT_STAGE, abase, 64, tid);
    asm volatile("cp.async.wait_group 1;" ::: "memory");   // KV0 ready
    __syncthreads();

    // Precomputed swizzled LDSM addresses (stage offset added per use).
    const uint32_t kb_base =
        (uint32_t)((((lane >> 4) * 8) + (lane & 7)) * 128 + ((lane >> 3) & 1) * 16);
    const int vr = (lane & 7) + ((lane >> 3) & 1) * 8;
    const uint32_t vcol = (uint32_t)((lane >> 4) * 16);
    uint32_t kaddr[4][4], vaddr[4][4];
#pragma unroll
    for (int kc = 0; kc < 4; kc++)
#pragma unroll
        for (int g = 0; g < 4; g++) {
            kaddr[kc][g] = swz(kb_base + g * 2048u + kc * 32u);
            vaddr[kc][g] = swz((uint32_t)((kc * 16 + vr) * 128) + vcol + g * 32u);
        }

    float oacc[8][4];
#pragma unroll
    for (int j = 0; j < 8; j++)
#pragma unroll
        for (int r = 0; r < 4; r++) oacc[j][r] = 0.f;
    float l0r = 0.f, l1r = 0.f;

    const float2* Bp = (const float2*)Bi;
    const int pairbase = warp * 8 + (lane >> 2);
    const int colbase = (lane & 3) << 1;

    for (int kt = 0; kt < NT; kt++) {
        const int k0 = kt * 64;
        const uint32_t so = (uint32_t)(kt & 1) * AT_STAGE;
        if (kt >= 1) {
            if (kt + 1 < NT) {
                attn_load_kv(sb, (uint32_t)((kt + 1) & 1) * AT_STAGE,
                             abase, (kt + 1) * 64, tid);
                asm volatile("cp.async.wait_group 1;" ::: "memory");
            } else {
                asm volatile("cp.async.wait_group 0;" ::: "memory");
            }
            __syncthreads();
        }
        const uint32_t kbase = sb + so + AT_KH;
        const uint32_t lbase = sb + so + AT_KL;
        const uint32_t vhb = sb + so + AT_VH;
        const uint32_t vlb = sb + so + AT_VL;

        // ---- S = Qs K^T (split-3) ----
        float sacc[8][4];
#pragma unroll
        for (int j = 0; j < 8; j++)
#pragma unroll
            for (int r = 0; r < 4; r++) sacc[j][r] = 0.f;

#pragma unroll
        for (int kc = 0; kc < 4; kc++) {
            uint32_t kh4[4][4], kl4[4][4];
#pragma unroll
            for (int g = 0; g < 4; g++)
                LDSM4(kh4[g], kbase + kaddr[kc][g]);
#pragma unroll
            for (int g = 0; g < 4; g++)
                LDSM4(kl4[g], lbase + kaddr[kc][g]);
#pragma unroll
            for (int g = 0; g < 4; g++) {
                MMA16816(sacc[2 * g + 0], qfh[kc], kh4[g][0], kh4[g][1]);
                MMA16816(sacc[2 * g + 1], qfh[kc], kh4[g][2], kh4[g][3]);
                MMA16816(sacc[2 * g + 0], qfl[kc], kh4[g][0], kh4[g][1]);
                MMA16816(sacc[2 * g + 1], qfl[kc], kh4[g][2], kh4[g][3]);
                MMA16816(sacc[2 * g + 0], qfh[kc], kl4[g][0], kl4[g][1]);
                MMA16816(sacc[2 * g + 1], qfh[kc], kl4[g][2], kl4[g][3]);
            }
        }

        // ---- bias + mask: packed coords via global uint2 (L1/L2 hit) ----
#pragma unroll
        for (int j = 0; j < 8; j++) {
            const int kg = k0 + 8 * j + colbase;
            const uint2 pc = *(const uint2*)(g_kcoord + kg);
            if (!(pc.x & 0x80000000u)) {
                const int khh = pc.x & 255, kww = (pc.x >> 8) & 255, ktt = pc.x >> 16;
                float2 vh = Bp[khh * 32 + pairbase];
                float2 vw = Bp[(14 + kww) * 32 + pairbase];
                float2 vt = Bp[(28 + ktt) * 32 + pairbase];
                sacc[j][0] += vh.x + vw.x + vt.x;
                sacc[j][2] += vh.y + vw.y + vt.y;
            } else {
                sacc[j][0] = -1e30f;
                sacc[j][2] = -1e30f;
            }
            if (!(pc.y & 0x80000000u)) {
                const int khh = pc.y & 255, kww = (pc.y >> 8) & 255, ktt = pc.y >> 16;
                float2 vh = Bp[khh * 32 + pairbase];
                float2 vw = Bp[(14 + kww) * 32 + pairbase];
                float2 vt = Bp[(28 + ktt) * 32 + pairbase];
                sacc[j][1] += vh.x + vw.x + vt.x;
                sacc[j][3] += vh.y + vw.y + vt.y;
            } else {
                sacc[j][1] = -1e30f;
                sacc[j][3] = -1e30f;
            }
        }

        // ---- fixed-max softmax: exp directly, accumulate denominator ----
#pragma unroll
        for (int j = 0; j < 8; j++) {
            sacc[j][0] = __expf(sacc[j][0]);
            sacc[j][1] = __expf(sacc[j][1]);
            sacc[j][2] = __expf(sacc[j][2]);
            sacc[j][3] = __expf(sacc[j][3]);
            l0r += sacc[j][0] + sacc[j][1];
            l1r += sacc[j][2] + sacc[j][3];
        }

        // ---- O += P V (split-3) ----
#pragma unroll
        for (int kc2 = 0; kc2 < 4; kc2++) {
            uint32_t ph[4], pl[4];
            split2(sacc[2 * kc2][0],     sacc[2 * kc2][1],     ph[0], pl[0]);
            split2(sacc[2 * kc2][2],     sacc[2 * kc2][3],     ph[1], pl[1]);
            split2(sacc[2 * kc2 + 1][0], sacc[2 * kc2 + 1][1], ph[2], pl[2]);
            split2(sacc[2 * kc2 + 1][2], sacc[2 * kc2 + 1][3], ph[3], pl[3]);
#pragma unroll
            for (int g = 0; g < 4; g++) {
                uint32_t vh4[4], vl4[4];
                LDSM4T(vh4, vhb + vaddr[kc2][g]);
                LDSM4T(vl4, vlb + vaddr[kc2][g]);
                MMA16816(oacc[2 * g + 0], ph, vh4[0], vh4[1]);
                MMA16816(oacc[2 * g + 1], ph, vh4[2], vh4[3]);
                MMA16816(oacc[2 * g + 0], pl, vh4[0], vh4[1]);
                MMA16816(oacc[2 * g + 1], pl, vh4[2], vh4[3]);
                MMA16816(oacc[2 * g + 0], ph, vl4[0], vl4[1]);
                MMA16816(oacc[2 * g + 1], ph, vl4[2], vl4[3]);
            }
        }
        __syncthreads();
    }

    // ---- single denominator reduction (across the 4 column lanes) ----
    l0r += __shfl_xor_sync(0xffffffffu, l0r, 1);
    l0r += __shfl_xor_sync(0xffffffffu, l0r, 2);
    l1r += __shfl_xor_sync(0xffffffffu, l1r, 1);
    l1r += __shfl_xor_sync(0xffffffffu, l1r, 2);

    // ---- epilogue: O / l -> split bf16 g_oh/g_ol at [b*N+q][h*64+d] ----
    const float inv0 = 1.f / l0r, inv1 = 1.f / l1r;
    const int qg0 = q0 + warp * 16 + (lane >> 2);
#pragma unroll
    for (int j = 0; j < 8; j++) {
        int d = 8 * j + colbase;
        if (qg0 < N_) {
            size_t off = ((size_t)b * N_ + qg0) * DIM_ + h * HD_ + d;
            uint32_t hi, lo;
            split2(oacc[j][0] * inv0, oacc[j][1] * inv0, hi, lo);
            *(uint32_t*)(g_oh + off) = hi;
            *(uint32_t*)(g_ol + off) = lo;
        }
        if (qg0 + 8 < N_) {
            size_t off = ((size_t)b * N_ + qg0 + 8) * DIM_ + h * HD_ + d;
            uint32_t hi, lo;
            split2(oacc[j][2] * inv1, oacc[j][3] * inv1, hi, lo);
            *(uint32_t*)(g_oh + off) = hi;
            *(uint32_t*)(g_ol + off) = lo;
        }
    }
}

// ---------------------------------------------------------------------------
extern "C" void kernel_launch(void* const* d_in, const int* in_sizes, int n_in,
                              void* d_out, int out_size) {
    (void)in_sizes; (void)n_in; (void)out_size;
    const float* x      = (const float*)d_in[0];
    const float* qkv_w  = (const float*)d_in[1];
    const float* proj_w = (const float*)d_in[2];
    const float* proj_b = (const float*)d_in[3];
    const float* rel_h  = (const float*)d_in[4];
    const float* rel_w  = (const float*)d_in[5];
    const float* rel_t  = (const float*)d_in[6];
    float* out = (float*)d_out;

    cudaFuncSetAttribute(mma_gemm,
                         cudaFuncAttributeMaxDynamicSharedMemorySize, GSMEM);
    cudaFuncSetAttribute(attn_tc,
                         cudaFuncAttributeMaxDynamicSharedMemorySize, AT_SMEM);

    // 0) merged hi/lo split conversions + k-coordinate table (one launch)
    split_all<<<(CVT_TOTAL + 255) / 256, 256>>>(x, qkv_w, proj_w);

    // 1) QKV projection -> fp32 g_q + split q/k/v attention arrays (fused)
    mma_gemm<<<dim3(3 * DIM_ / 128, MPAD / 128), 256, GSMEM>>>(0, nullptr, nullptr);

    // 2) Decomposed rel-pos bias tables (unscaled q)
    relbias<<<(B_ * HEADS_ * N_ + 7) / 8, 256>>>(rel_h, rel_w, rel_t);

    // 3) Tensor-core flash attention (3 CTAs/SM)
    attn_tc<<<dim3(NPAD / 64, HEADS_, B_), 128, AT_SMEM>>>();

    // 4) Output projection
    mma_gemm<<<dim3(DIM_ / 128, MPAD / 128), 256, GSMEM>>>(1, proj_b, out);
}

// round 17
// speedup vs baseline: 1.0381x; 1.0381x over previous
#include <cuda_runtime.h>
#include <cuda_bf16.h>
#include <cstdint>

// Problem constants
#define B_     2
#define T_     8
#define H_     14
#define W_     14
#define S_     196          // H_*W_
#define N_     1568         // T_*S_
#define NPAD   1600         // padded rows per (b,h): 25 * 64
#define DIM_   768
#define HEADS_ 12
#define HD_    64
#define MROWS  (B_ * N_)    // 3136
#define MPAD   3200         // 25 * 128
#define NBIAS  36           // 14 (h) + 14 (w) + 8 (t)

// fp32 scratch (q needed for relbias)
__device__ float g_q[(size_t)B_ * HEADS_ * N_ * HD_];
__device__ float g_bias[(size_t)B_ * HEADS_ * N_ * NBIAS];
// packed k coordinates: kh | kw<<8 | kt<<16, bit31 = out-of-range
__device__ uint32_t g_kcoord[NPAD];

// split-bf16 scratch for the two projection GEMMs
__device__ __nv_bfloat16 g_xh[(size_t)MPAD * DIM_];
__device__ __nv_bfloat16 g_xl[(size_t)MPAD * DIM_];
__device__ __nv_bfloat16 g_wh[(size_t)3 * DIM_ * DIM_];
__device__ __nv_bfloat16 g_wl[(size_t)3 * DIM_ * DIM_];
__device__ __nv_bfloat16 g_ph[(size_t)DIM_ * DIM_];
__device__ __nv_bfloat16 g_pl[(size_t)DIM_ * DIM_];
// attention output, split (pad rows stay statically zero — never written)
__device__ __nv_bfloat16 g_oh[(size_t)MPAD * DIM_];
__device__ __nv_bfloat16 g_ol[(size_t)MPAD * DIM_];

// split-bf16 attention operands (padded; pad rows statically zero)
// K needs only the hi part (Qh*Kl term dropped; Ql*Kh kept).
#define ASZ ((size_t)B_ * HEADS_ * NPAD * HD_)
__device__ __nv_bfloat16 g_aqh[ASZ], g_aql[ASZ];   // Q pre-scaled by 0.125
__device__ __nv_bfloat16 g_akh[ASZ];
__device__ __nv_bfloat16 g_avh[ASZ], g_avl[ASZ];

// ---------------------------------------------------------------------------
// Helpers (sm_80-family only — compile clean to plain compute_103)
// ---------------------------------------------------------------------------
__device__ __forceinline__ uint32_t smem_u32(const void* p) {
    uint32_t a;
    asm("{ .reg .u64 t; cvta.to.shared.u64 t, %1; cvt.u32.u64 %0, t; }"
        : "=r"(a) : "l"(p));
    return a;
}

__device__ __forceinline__ uint32_t swz(uint32_t x) {
    return x ^ ((x >> 3) & 0x70);
}

#define CP_ASYNC16(s, g) \
    asm volatile("cp.async.cg.shared.global [%0], [%1], 16;" :: "r"(s), "l"(g))

#define LDSM4(r, a) \
    asm volatile("ldmatrix.sync.aligned.m8n8.x4.shared.b16 {%0,%1,%2,%3}, [%4];" \
        : "=r"((r)[0]), "=r"((r)[1]), "=r"((r)[2]), "=r"((r)[3]) : "r"(a))

#define LDSM4T(r, a) \
    asm volatile("ldmatrix.sync.aligned.m8n8.x4.trans.shared.b16 {%0,%1,%2,%3}, [%4];" \
        : "=r"((r)[0]), "=r"((r)[1]), "=r"((r)[2]), "=r"((r)[3]) : "r"(a))

#define MMA16816(d, a, b0, b1) \
    asm volatile("mma.sync.aligned.m16n8k16.row.col.f32.bf16.bf16.f32 " \
        "{%0,%1,%2,%3},{%4,%5,%6,%7},{%8,%9},{%0,%1,%2,%3};" \
        : "+f"((d)[0]), "+f"((d)[1]), "+f"((d)[2]), "+f"((d)[3]) \
        : "r"((a)[0]), "r"((a)[1]), "r"((a)[2]), "r"((a)[3]), "r"(b0), "r"(b1))

// pack two fp32 into bf16x2 hi/lo split (fast: packed cvt + shift/sub)
__device__ __forceinline__ void split2(float p0, float p1,
                                       uint32_t& hi, uint32_t& lo) {
    uint32_t h;
    asm("cvt.rn.bf16x2.f32 %0, %1, %2;" : "=r"(h) : "f"(p1), "f"(p0));
    float h0 = __uint_as_float(h << 16);
    float h1 = __uint_as_float(h & 0xffff0000u);
    float l0 = p0 - h0, l1 = p1 - h1;
    asm("cvt.rn.bf16x2.f32 %0, %1, %2;" : "=r"(lo) : "f"(l1), "f"(l0));
    hi = h;
}

// pack two fp32 into bf16x2 (hi only)
__device__ __forceinline__ uint32_t pack2(float p0, float p1) {
    uint32_t h;
    asm("cvt.rn.bf16x2.f32 %0, %1, %2;" : "=r"(h) : "f"(p1), "f"(p0));
    return h;
}

// ---------------------------------------------------------------------------
// Merged split conversion (one launch):
//   [0, CVT_NXP)   : x      -> g_xh/g_xl  (pad rows zero)
//   [+CVT_NW)      : qkv_w  -> g_wh/g_wl
//   [+CVT_NP)      : proj_w -> g_ph/g_pl
//   [+NPAD)        : packed k-coordinate table g_kcoord
// ---------------------------------------------------------------------------
#define CVT_NX  (MROWS * DIM_)
#define CVT_NXP (MPAD * DIM_)
#define CVT_NW  (3 * DIM_ * DIM_)
#define CVT_NP  (DIM_ * DIM_)
#define CVT_TOTAL (CVT_NXP + CVT_NW + CVT_NP + NPAD)

__global__ __launch_bounds__(256) void split_all(const float* __restrict__ x,
                                                 const float* __restrict__ qw,
                                                 const float* __restrict__ pw) {
    int i = blockIdx.x * blockDim.x + threadIdx.x;
    if (i >= CVT_TOTAL) return;
    if (i >= CVT_NXP + CVT_NW + CVT_NP) {
        int kg = i - (CVT_NXP + CVT_NW + CVT_NP);
        uint32_t pc = 0x80000000u;
        if (kg < N_) {
            int ktt = kg / S_;
            int krem = kg - ktt * S_;
            int khh = krem / W_;
            int kww = krem - khh * W_;
            pc = (uint32_t)khh | ((uint32_t)kww << 8) | ((uint32_t)ktt << 16);
        }
        g_kcoord[kg] = pc;
        return;
    }
    float v;
    __nv_bfloat16 *hi, *lo;
    int o;
    if (i < CVT_NXP) {
        o = i;
        v = (o < CVT_NX) ? x[o] : 0.f;
        hi = g_xh; lo = g_xl;
    } else if (i < CVT_NXP + CVT_NW) {
        o = i - CVT_NXP;
        v = qw[o];
        hi = g_wh; lo = g_wl;
    } else {
        o = i - CVT_NXP - CVT_NW;
        v = pw[o];
        hi = g_ph; lo = g_pl;
    }
    __nv_bfloat16 h = __float2bfloat16(v);
    hi[o] = h;
    lo[o] = __float2bfloat16(v - __bfloat162float(h));
}

// ---------------------------------------------------------------------------
// Warp-MMA split-bf16 GEMM, single-buffered 64KB smem (R11 path).
// ---------------------------------------------------------------------------
#define OFF_AH 0u
#define OFF_AL 16384u
#define OFF_BH 32768u
#define OFF_BL 49152u
#define GSMEM  65536

__device__ __forceinline__ void gemm_load(uint32_t sb,
        const __nv_bfloat16* Ahp, const __nv_bfloat16* Alp,
        const __nv_bfloat16* Bhp, const __nv_bfloat16* Blp,
        int m0, int n0, int k0, int tid) {
    const int grow = tid >> 3, gch = tid & 7;
#pragma unroll
    for (int p = 0; p < 4; p++) {
        int row = grow + p * 32;
        uint32_t sw = swz((uint32_t)(row * 128 + gch * 16));
        size_t ga = (size_t)(m0 + row) * DIM_ + k0 + gch * 8;
        size_t gb = (size_t)(n0 + row) * DIM_ + k0 + gch * 8;
        CP_ASYNC16(sb + OFF_AH + sw, Ahp + ga);
        CP_ASYNC16(sb + OFF_AL + sw, Alp + ga);
        CP_ASYNC16(sb + OFF_BH + sw, Bhp + gb);
        CP_ASYNC16(sb + OFF_BL + sw, Blp + gb);
    }
    asm volatile("cp.async.commit_group;");
}

__global__ __launch_bounds__(256, 2) void mma_gemm(int mode,
                                                   const float* __restrict__ pb,
                                                   float* __restrict__ out) {
    extern __shared__ char sm[];
    const uint32_t sb = smem_u32(sm);
    const int tid = threadIdx.x;
    const int lane = tid & 31, wid = tid >> 5;
    const int wm = wid & 3;
    const int wn = wid >> 2;
    const int m0 = blockIdx.y * 128;
    const int n0 = blockIdx.x * 128;

    const __nv_bfloat16* Ahp = (mode == 0) ? g_xh : g_oh;
    const __nv_bfloat16* Alp = (mode == 0) ? g_xl : g_ol;
    const __nv_bfloat16* Bhp = (mode == 0) ? g_wh : g_ph;
    const __nv_bfloat16* Blp = (mode == 0) ? g_wl : g_pl;

    float acc[2][8][4];
#pragma unroll
    for (int a = 0; a < 2; a++)
#pragma unroll
        for (int na = 0; na < 8; na++)
#pragma unroll
            for (int r = 0; r < 4; r++) acc[a][na][r] = 0.f;

    const int ar = lane & 15, akh = lane >> 4;
    const uint32_t a_base = (uint32_t)((wm * 32 + ar) * 128 + akh * 16);
    const int br = lane & 7, bsel = lane >> 3;
    const uint32_t b_base =
        (uint32_t)((wn * 64 + (bsel >> 1) * 8 + br) * 128 + (bsel & 1) * 16);

    for (int c = 0; c < DIM_ / 64; c++) {
        gemm_load(sb, Ahp, Alp, Bhp, Blp, m0, n0, c * 64, tid);
        asm volatile("cp.async.wait_group 0;" ::: "memory");
        __syncthreads();

#pragma unroll
        for (int ks = 0; ks < 4; ks++) {
            const uint32_t kb = ks * 32;
            uint32_t ah[2][4], bh[4][4];
#pragma unroll
            for (int a = 0; a < 2; a++)
                LDSM4(ah[a], sb + OFF_AH + swz(a_base + a * 2048 + kb));
#pragma unroll
            for (int g = 0; g < 4; g++)
                LDSM4(bh[g], sb + OFF_BH + swz(b_base + g * 2048 + kb));
#pragma unroll
            for (int a = 0; a < 2; a++)
#pragma unroll
                for (int g = 0; g < 4; g++) {
                    MMA16816(acc[a][2 * g + 0], ah[a], bh[g][0], bh[g][1]);
                    MMA16816(acc[a][2 * g + 1], ah[a], bh[g][2], bh[g][3]);
                }
            {
                uint32_t al[2][4];
#pragma unroll
                for (int a = 0; a < 2; a++)
                    LDSM4(al[a], sb + OFF_AL + swz(a_base + a * 2048 + kb));
#pragma unroll
                for (int a = 0; a < 2; a++)
#pragma unroll
                    for (int g = 0; g < 4; g++) {
                        MMA16816(acc[a][2 * g + 0], al[a], bh[g][0], bh[g][1]);
                        MMA16816(acc[a][2 * g + 1], al[a], bh[g][2], bh[g][3]);
                    }
            }
#pragma unroll
            for (int g = 0; g < 4; g++)
                LDSM4(bh[g], sb + OFF_BL + swz(b_base + g * 2048 + kb));
#pragma unroll
            for (int a = 0; a < 2; a++)
#pragma unroll
                for (int g = 0; g < 4; g++) {
                    MMA16816(acc[a][2 * g + 0], ah[a], bh[g][0], bh[g][1]);
                    MMA16816(acc[a][2 * g + 1], ah[a], bh[g][2], bh[g][3]);
                }
        }
        __syncthreads();
    }

    const int mr = m0 + wm * 32 + lane / 4;
    const int nc0 = (lane & 3) * 2;
    if (mode == 0) {
        const int ncb = n0 + wn * 64;
        const int s = ncb / DIM_;                 // 0=q,1=k,2=v
        const int head = (ncb % DIM_) / HD_;
#pragma unroll
        for (int a = 0; a < 2; a++)
#pragma unroll
            for (int hf = 0; hf < 2; hf++) {
                int m = mr + a * 16 + hf * 8;
                if (m < MROWS) {
                    int bb = m / N_;
                    int nn = m - bb * N_;
                    size_t bh = (size_t)bb * HEADS_ + head;
                    size_t arow = (bh * NPAD + nn) * HD_;
#pragma unroll
                    for (int na = 0; na < 8; na++) {
                        int col = na * 8 + nc0;
                        float v0 = acc[a][na][hf * 2];
                        float v1 = acc[a][na][hf * 2 + 1];
                        uint32_t hi, lo;
                        if (s == 0) {
                            float* qrow = g_q + (bh * N_ + nn) * HD_;
                            qrow[col] = v0; qrow[col + 1] = v1;   // unscaled (relbias)
                            split2(v0 * 0.125f, v1 * 0.125f, hi, lo);
                            *(uint32_t*)(g_aqh + arow + col) = hi;
                            *(uint32_t*)(g_aql + arow + col) = lo;
                        } else if (s == 1) {
                            // K: hi part only (Qh*Kl term dropped)
                            *(uint32_t*)(g_akh + arow + col) = pack2(v0, v1);
                        } else {
                            split2(v0, v1, hi, lo);
                            *(uint32_t*)(g_avh + arow + col) = hi;
                            *(uint32_t*)(g_avl + arow + col) = lo;
                        }
                    }
                }
            }
    } else {
        const int ncb = n0 + wn * 64;
#pragma unroll
        for (int a = 0; a < 2; a++)
#pragma unroll
            for (int hf = 0; hf < 2; hf++) {
                int m = mr + a * 16 + hf * 8;
                if (m < MROWS) {
                    float* orow = out + (size_t)m * DIM_ + ncb;
#pragma unroll
                    for (int na = 0; na < 8; na++) {
                        int cc = na * 8 + nc0;
                        orow[cc]     = acc[a][na][hf * 2]     + pb[ncb + cc];
                        orow[cc + 1] = acc[a][na][hf * 2 + 1] + pb[ncb + cc + 1];
                    }
                }
            }
    }
}

// ---------------------------------------------------------------------------
// Relative position bias precompute (one warp per (b,h,q); unscaled q).
// ---------------------------------------------------------------------------
__global__ __launch_bounds__(256) void relbias(const float* __restrict__ rel_h,
                                               const float* __restrict__ rel_w,
                                               const float* __restrict__ rel_t) {
    const int warp = (blockIdx.x * blockDim.x + threadIdx.x) >> 5;
    const int lane = threadIdx.x & 31;
    if (warp >= B_ * HEADS_ * N_) return;
    const int q = warp % N_;
    const int qt = q / S_;
    const int qrem = q - qt * S_;
    const int qh = qrem / W_;
    const int qw = qrem - qh * W_;

    const float* qv = g_q + (size_t)warp * HD_;
    const float qa = qv[lane];
    const float qb = qv[lane + 32];
    float* out = g_bias + (size_t)warp * NBIAS;

#pragma unroll 4
    for (int j = 0; j < NBIAS; j++) {
        const float* r;
        if (j < 14)       r = rel_h + (size_t)(qh - j + 13) * HD_;
        else if (j < 28)  r = rel_w + (size_t)(qw - (j - 14) + 13) * HD_;
        else              r = rel_t + (size_t)(qt - (j - 28) + 7) * HD_;
        float p = qa * r[lane] + qb * r[lane + 32];
#pragma unroll
        for (int m = 16; m >= 1; m >>= 1) p += __shfl_xor_sync(0xffffffffu, p, m);
        if (lane == 0) out[j] = p;
    }
}

// ---------------------------------------------------------------------------
// Tensor-core flash attention (R14 base, K-lo term dropped):
//  - QK^T split-2: Qh*Kh + Ql*Kh  (Qh*Kl dropped — error ~3e-4 on scores)
//  - fixed-max softmax, paired float2 bias, packed k-coord smem table
//  - PV stays split-3 (accuracy-critical)
// ---------------------------------------------------------------------------
#define AT_KH 0u
#define AT_VH 8192u
#define AT_VL 16384u
#define AT_STAGE 24576u
#define AT_QH 49152u
#define AT_QL 57344u
#define AT_BI 65536u
#define AT_KC (65536u + 64u * NBIAS * 4u)          // 74752
#define AT_SMEM (74752 + NPAD * 4)                 // 81152

__device__ __forceinline__ void attn_load_kv(uint32_t sb, uint32_t so,
                                             size_t abase, int k0, int tid) {
#pragma unroll
    for (int p = 0; p < 4; p++) {
        int idx = tid + p * 128;
        int row = idx >> 3, ch = idx & 7;
        uint32_t sw = swz((uint32_t)(row * 128 + ch * 16));
        size_t g = abase + (size_t)(k0 + row) * HD_ + ch * 8;
        CP_ASYNC16(sb + so + AT_KH + sw, g_akh + g);
        CP_ASYNC16(sb + so + AT_VH + sw, g_avh + g);
        CP_ASYNC16(sb + so + AT_VL + sw, g_avl + g);
    }
    asm volatile("cp.async.commit_group;");
}

__global__ __launch_bounds__(128) void attn_tc() {
    extern __shared__ char sm[];
    const uint32_t sb = smem_u32(sm);
    float* Bi = (float*)(sm + AT_BI);
    uint32_t* KcoS = (uint32_t*)(sm + AT_KC);
    const int b = blockIdx.z, h = blockIdx.y, q0 = blockIdx.x * 64;
    const int tid = threadIdx.x, lane = tid & 31, warp = tid >> 5;
    const size_t bh = (size_t)b * HEADS_ + h;
    const size_t abase = bh * NPAD * HD_;
    const int NT = NPAD / 64;                 // 25 k-tiles

    // Group A: Q tiles (hi/lo) + KV tile 0 (stage 0)
#pragma unroll
    for (int p = 0; p < 4; p++) {
        int idx = tid + p * 128;
        int row = idx >> 3, ch = idx & 7;
        uint32_t sw = swz((uint32_t)(row * 128 + ch * 16));
        size_t g = abase + (size_t)(q0 + row) * HD_ + ch * 8;
        CP_ASYNC16(sb + AT_QH + sw, g_aqh + g);
        CP_ASYNC16(sb + AT_QL + sw, g_aql + g);
        size_t gk = abase + (size_t)row * HD_ + ch * 8;
        CP_ASYNC16(sb + AT_KH + sw, g_akh + gk);
        CP_ASYNC16(sb + AT_VH + sw, g_avh + gk);
        CP_ASYNC16(sb + AT_VL + sw, g_avl + gk);
    }
    // Bias into paired layout: Bi2[(j*32 + pair)*2 + half], pair rows (r, r+8)
    for (int i = tid; i < 64 * NBIAS; i += 128) {
        int qr = i / NBIAS, j = i - qr * NBIAS;
        int qg = q0 + qr;
        float v = (qg < N_) ? g_bias[(bh * N_ + qg) * NBIAS + j] : 0.f;
        int wq = qr >> 4, within = qr & 15;
        int half = within >> 3, sub = within & 7;
        Bi[(j * 32 + wq * 8 + sub) * 2 + half] = v;
    }
    for (int i = tid; i < NPAD; i += 128) KcoS[i] = g_kcoord[i];
    asm volatile("cp.async.commit_group;");
    // Group B: prefetch KV tile 1 (stage 1)
    attn_load_kv(sb, AT_STAGE, abase, 64, tid);
    asm volatile("cp.async.wait_group 1;" ::: "memory");   // group A done
    __syncthreads();

    // Q fragments (held for the whole kernel)
    uint32_t qfh[4][4], qfl[4][4];
    {
        const uint32_t a_base =
            (uint32_t)((warp * 16 + (lane & 15)) * 128 + (lane >> 4) * 16);
#pragma unroll
        for (int kc = 0; kc < 4; kc++) {
            LDSM4(qfh[kc], sb + AT_QH + swz(a_base + kc * 32));
            LDSM4(qfl[kc], sb + AT_QL + swz(a_base + kc * 32));
        }
    }

    // Precomputed swizzled LDSM addresses (stage offset added per use).
    const uint32_t kb_base =
        (uint32_t)((((lane >> 4) * 8) + (lane & 7)) * 128 + ((lane >> 3) & 1) * 16);
    const int vr = (lane & 7) + ((lane >> 3) & 1) * 8;
    const uint32_t vcol = (uint32_t)((lane >> 4) * 16);
    uint32_t kaddr[4][4], vaddr[4][4];
#pragma unroll
    for (int kc = 0; kc < 4; kc++)
#pragma unroll
        for (int g = 0; g < 4; g++) {
            kaddr[kc][g] = swz(kb_base + g * 2048u + kc * 32u);
            vaddr[kc][g] = swz((uint32_t)((kc * 16 + vr) * 128) + vcol + g * 32u);
        }

    float oacc[8][4];
#pragma unroll
    for (int j = 0; j < 8; j++)
#pragma unroll
        for (int r = 0; r < 4; r++) oacc[j][r] = 0.f;
    float l0r = 0.f, l1r = 0.f;

    const float2* Bp = (const float2*)Bi;
    const int pairbase = warp * 8 + (lane >> 2);
    const int colbase = (lane & 3) << 1;

    for (int kt = 0; kt < NT; kt++) {
        const int k0 = kt * 64;
        const uint32_t so = (uint32_t)(kt & 1) * AT_STAGE;
        if (kt >= 1) {
            if (kt + 1 < NT) {
                attn_load_kv(sb, (uint32_t)((kt + 1) & 1) * AT_STAGE,
                             abase, (kt + 1) * 64, tid);
                asm volatile("cp.async.wait_group 1;" ::: "memory");
            } else {
                asm volatile("cp.async.wait_group 0;" ::: "memory");
            }
            __syncthreads();
        }
        const uint32_t kbase = sb + so + AT_KH;
        const uint32_t vhb = sb + so + AT_VH;
        const uint32_t vlb = sb + so + AT_VL;

        // ---- S = Qs K^T (split-2: (Qh+Ql) * Kh) ----
        float sacc[8][4];
#pragma unroll
        for (int j = 0; j < 8; j++)
#pragma unroll
            for (int r = 0; r < 4; r++) sacc[j][r] = 0.f;

#pragma unroll
        for (int kc = 0; kc < 4; kc++) {
            uint32_t kh4[4][4];
#pragma unroll
            for (int g = 0; g < 4; g++)
                LDSM4(kh4[g], kbase + kaddr[kc][g]);
#pragma unroll
            for (int g = 0; g < 4; g++) {
                MMA16816(sacc[2 * g + 0], qfh[kc], kh4[g][0], kh4[g][1]);
                MMA16816(sacc[2 * g + 1], qfh[kc], kh4[g][2], kh4[g][3]);
                MMA16816(sacc[2 * g + 0], qfl[kc], kh4[g][0], kh4[g][1]);
                MMA16816(sacc[2 * g + 1], qfl[kc], kh4[g][2], kh4[g][3]);
            }
        }

        // ---- bias + mask via packed coord table + paired float2 loads ----
#pragma unroll
        for (int j = 0; j < 8; j++) {
            const int kg = k0 + 8 * j + colbase;
            const uint32_t pc0 = KcoS[kg];
            const uint32_t pc1 = KcoS[kg + 1];
            if (!(pc0 & 0x80000000u)) {
                const int khh = pc0 & 255, kww = (pc0 >> 8) & 255, ktt = pc0 >> 16;
                float2 vh = Bp[khh * 32 + pairbase];
                float2 vw = Bp[(14 + kww) * 32 + pairbase];
                float2 vt = Bp[(28 + ktt) * 32 + pairbase];
                sacc[j][0] += vh.x + vw.x + vt.x;
                sacc[j][2] += vh.y + vw.y + vt.y;
            } else {
                sacc[j][0] = -1e30f;
                sacc[j][2] = -1e30f;
            }
            if (!(pc1 & 0x80000000u)) {
                const int khh = pc1 & 255, kww = (pc1 >> 8) & 255, ktt = pc1 >> 16;
                float2 vh = Bp[khh * 32 + pairbase];
                float2 vw = Bp[(14 + kww) * 32 + pairbase];
                float2 vt = Bp[(28 + ktt) * 32 + pairbase];
                sacc[j][1] += vh.x + vw.x + vt.x;
                sacc[j][3] += vh.y + vw.y + vt.y;
            } else {
                sacc[j][1] = -1e30f;
                sacc[j][3] = -1e30f;
            }
        }

        // ---- fixed-max softmax: exp directly, accumulate denominator ----
#pragma unroll
        for (int j = 0; j < 8; j++) {
            sacc[j][0] = __expf(sacc[j][0]);
            sacc[j][1] = __expf(sacc[j][1]);
            sacc[j][2] = __expf(sacc[j][2]);
            sacc[j][3] = __expf(sacc[j][3]);
            l0r += sacc[j][0] + sacc[j][1];
            l1r += sacc[j][2] + sacc[j][3];
        }

        // ---- O += P V (split-3) ----
#pragma unroll
        for (int kc2 = 0; kc2 < 4; kc2++) {
            uint32_t ph[4], pl[4];
            split2(sacc[2 * kc2][0],     sacc[2 * kc2][1],     ph[0], pl[0]);
            split2(sacc[2 * kc2][2],     sacc[2 * kc2][3],     ph[1], pl[1]);
            split2(sacc[2 * kc2 + 1][0], sacc[2 * kc2 + 1][1], ph[2], pl[2]);
            split2(sacc[2 * kc2 + 1][2], sacc[2 * kc2 + 1][3], ph[3], pl[3]);
#pragma unroll
            for (int g = 0; g < 4; g++) {
                uint32_t vh4[4], vl4[4];
                LDSM4T(vh4, vhb + vaddr[kc2][g]);
                LDSM4T(vl4, vlb + vaddr[kc2][g]);
                MMA16816(oacc[2 * g + 0], ph, vh4[0], vh4[1]);
                MMA16816(oacc[2 * g + 1], ph, vh4[2], vh4[3]);
                MMA16816(oacc[2 * g + 0], pl, vh4[0], vh4[1]);
                MMA16816(oacc[2 * g + 1], pl, vh4[2], vh4[3]);
                MMA16816(oacc[2 * g + 0], ph, vl4[0], vl4[1]);
                MMA16816(oacc[2 * g + 1], ph, vl4[2], vl4[3]);
            }
        }
        __syncthreads();
    }

    // ---- single denominator reduction (across the 4 column lanes) ----
    l0r += __shfl_xor_sync(0xffffffffu, l0r, 1);
    l0r += __shfl_xor_sync(0xffffffffu, l0r, 2);
    l1r += __shfl_xor_sync(0xffffffffu, l1r, 1);
    l1r += __shfl_xor_sync(0xffffffffu, l1r, 2);

    // ---- epilogue: O / l -> split bf16 g_oh/g_ol at [b*N+q][h*64+d] ----
    const float inv0 = 1.f / l0r, inv1 = 1.f / l1r;
    const int qg0 = q0 + warp * 16 + (lane >> 2);
#pragma unroll
    for (int j = 0; j < 8; j++) {
        int d = 8 * j + colbase;
        if (qg0 < N_) {
            size_t off = ((size_t)b * N_ + qg0) * DIM_ + h * HD_ + d;
            uint32_t hi, lo;
            split2(oacc[j][0] * inv0, oacc[j][1] * inv0, hi, lo);
            *(uint32_t*)(g_oh + off) = hi;
            *(uint32_t*)(g_ol + off) = lo;
        }
        if (qg0 + 8 < N_) {
            size_t off = ((size_t)b * N_ + qg0 + 8) * DIM_ + h * HD_ + d;
            uint32_t hi, lo;
            split2(oacc[j][2] * inv1, oacc[j][3] * inv1, hi, lo);
            *(uint32_t*)(g_oh + off) = hi;
            *(uint32_t*)(g_ol + off) = lo;
        }
    }
}

// ---------------------------------------------------------------------------
extern "C" void kernel_launch(void* const* d_in, const int* in_sizes, int n_in,
                              void* d_out, int out_size) {
    (void)in_sizes; (void)n_in; (void)out_size;
    const float* x      = (const float*)d_in[0];
    const float* qkv_w  = (const float*)d_in[1];
    const float* proj_w = (const float*)d_in[2];
    const float* proj_b = (const float*)d_in[3];
    const float* rel_h  = (const float*)d_in[4];
    const float* rel_w  = (const float*)d_in[5];
    const float* rel_t  = (const float*)d_in[6];
    float* out = (float*)d_out;

    cudaFuncSetAttribute(mma_gemm,
                         cudaFuncAttributeMaxDynamicSharedMemorySize, GSMEM);
    cudaFuncSetAttribute(attn_tc,
                         cudaFuncAttributeMaxDynamicSharedMemorySize, AT_SMEM);

    // 0) merged hi/lo split conversions + k-coordinate table (one launch)
    split_all<<<(CVT_TOTAL + 255) / 256, 256>>>(x, qkv_w, proj_w);

    // 1) QKV projection -> fp32 g_q + split q/k/v attention arrays (fused)
    mma_gemm<<<dim3(3 * DIM_ / 128, MPAD / 128), 256, GSMEM>>>(0, nullptr, nullptr);

    // 2) Decomposed rel-pos bias tables (unscaled q)
    relbias<<<(B_ * HEADS_ * N_ + 7) / 8, 256>>>(rel_h, rel_w, rel_t);

    // 3) Tensor-core flash attention (QK split-2, PV split-3)
    attn_tc<<<dim3(NPAD / 64, HEADS_, B_), 128, AT_SMEM>>>();

    // 4) Output projection
    mma_gemm<<<dim3(DIM_ / 128, MPAD / 128), 256, GSMEM>>>(1, proj_b, out);
}